// round 12
// baseline (speedup 1.0000x reference)
#include <cuda_runtime.h>
#include <cuda_bf16.h>
#include <cstdint>

#define N_ROWS   16384
#define DIMS     256
#define K_CODES  8192
#define OUT_ELEMS 4194304
#define LOSS_OFF  4194304
#define IDX_OFF   4194305
#define NGROUP   512           // 8192 codes / 16 per lane-local group
#define MARGIN   0.125f

// device scratch (allocation-free rule)
__device__ float g_xr[N_ROWS * DIMS];            // transposed x fp32
__device__ __nv_bfloat16 g_xb[N_ROWS * DIMS];    // transposed x bf16
__device__ __nv_bfloat16 g_ebh[K_CODES * DIMS];  // E bf16
__device__ float g_xx[N_ROWS];
__device__ float g_ce[K_CODES];
__device__ __nv_bfloat16 g_cmin[N_ROWS * NGROUP]; // approx lane-group mins
__device__ int   g_idx[N_ROWS];
__device__ float g_minv[N_ROWS];                  // winning distance per row

// ---------------- PTX helpers ----------------
static __device__ __forceinline__ uint32_t smem_u32(const void* p) {
    uint32_t a;
    asm("{ .reg .u64 t; cvta.to.shared.u64 t, %1; cvt.u32.u64 %0, t; }"
        : "=r"(a) : "l"(p));
    return a;
}
#define CP16(dst, src) asm volatile("cp.async.cg.shared.global [%0], [%1], 16;" :: "r"(dst), "l"(src))
#define CP_COMMIT()    asm volatile("cp.async.commit_group;" ::: "memory")
#define CP_WAIT0()     asm volatile("cp.async.wait_group 0;" ::: "memory")

#define LDSM_X4(r0, r1, r2, r3, a) \
    asm volatile("ldmatrix.sync.aligned.m8n8.x4.shared.b16 {%0,%1,%2,%3}, [%4];" \
        : "=r"(r0), "=r"(r1), "=r"(r2), "=r"(r3) : "r"(a))
#define MMA16816(d, a, b) \
    asm volatile("mma.sync.aligned.m16n8k16.row.col.f32.bf16.bf16.f32 " \
        "{%0,%1,%2,%3}, {%4,%5,%6,%7}, {%8,%9}, {%0,%1,%2,%3};" \
        : "+f"((d)[0]), "+f"((d)[1]), "+f"((d)[2]), "+f"((d)[3]) \
        : "r"((a)[0]), "r"((a)[1]), "r"((a)[2]), "r"((a)[3]), "r"((b)[0]), "r"((b)[1]))

// swizzled 16B-unit offset within a [rows x 512B] tile
static __device__ __forceinline__ uint32_t sw_off(int r, int u) {
    return ((uint32_t)r << 9) + (uint32_t)(((u ^ (r & 7)) & 31) << 4);
}

// SMEM map for k_gemm (bytes): X up to 112 rows (56KB), E stages 64KB each, ce 32KB
#define SM_X   0
#define SM_E0  57344
#define SM_E1  122880
#define SM_CE  188416
#define SMEM_SZ 221184

// ---------------------------------------------------------------------------
// 1) fused transpose + xx + bf16: x [b,c,h,w] -> g_xr, g_xb, g_xx
__global__ void k_trx(const float* __restrict__ x) {
    __shared__ float t[256][33];
    __shared__ float sxx[8][33];
    const int b = blockIdx.y, hw0 = blockIdx.x * 32;
    const int tx = threadIdx.x, ty = threadIdx.y;
    const int tid = ty * 32 + tx;
    const int n0 = b * 1024 + hw0;

    float px = 0.f;
#pragma unroll
    for (int j = 0; j < 32; j++) {
        int c = ty + j * 8;
        float v = x[(size_t)b * 262144 + (size_t)c * 1024 + hw0 + tx];
        t[c][tx] = v;
        px = fmaf(v, v, px);
    }
    sxx[ty][tx] = px;
    __syncthreads();

#pragma unroll
    for (int r = 0; r < 32; r++) {
        float v = t[tid][r];
        g_xr[(size_t)(n0 + r) * DIMS + tid] = v;
        g_xb[(size_t)(n0 + r) * DIMS + tid] = __float2bfloat16_rn(v);
    }
    if (tid < 32) {
        float s = 0.f;
#pragma unroll
        for (int j = 0; j < 8; j++) s += sxx[j][tid];
        g_xx[n0 + tid] = s;
    }
}

// 2) E prep: ||e||^2 + bf16 convert (one warp per code row)
__global__ void k_prep_e(const float* __restrict__ e) {
    int w = threadIdx.x >> 5, lane = threadIdx.x & 31;
    int row = blockIdx.x * 8 + w;
    const float4* p = (const float4*)(e + (size_t)row * DIMS);
    float4 v0 = p[lane], v1 = p[lane + 32];
    float s = v0.x * v0.x + v0.y * v0.y + v0.z * v0.z + v0.w * v0.w +
              v1.x * v1.x + v1.y * v1.y + v1.z * v1.z + v1.w * v1.w;
    uint2* q = (uint2*)(g_ebh + (size_t)row * DIMS);
    uint32_t a0 = ((uint32_t)__bfloat16_as_ushort(__float2bfloat16_rn(v0.y)) << 16) |
                  (uint32_t)__bfloat16_as_ushort(__float2bfloat16_rn(v0.x));
    uint32_t a1 = ((uint32_t)__bfloat16_as_ushort(__float2bfloat16_rn(v0.w)) << 16) |
                  (uint32_t)__bfloat16_as_ushort(__float2bfloat16_rn(v0.z));
    uint32_t b0 = ((uint32_t)__bfloat16_as_ushort(__float2bfloat16_rn(v1.y)) << 16) |
                  (uint32_t)__bfloat16_as_ushort(__float2bfloat16_rn(v1.x));
    uint32_t b1 = ((uint32_t)__bfloat16_as_ushort(__float2bfloat16_rn(v1.w)) << 16) |
                  (uint32_t)__bfloat16_as_ushort(__float2bfloat16_rn(v1.z));
    q[lane] = make_uint2(a0, a1);
    q[lane + 32] = make_uint2(b0, b1);
#pragma unroll
    for (int off = 16; off; off >>= 1) s += __shfl_xor_sync(0xffffffffu, s, off);
    if (lane == 0) g_ce[row] = s;
}

// ---------------------------------------------------------------------------
// 3) Sweep 1: bf16 mma.sync GEMM, balanced grid of 148 CTAs:
//    CTAs 0..135 own 7 m-tiles (112 rows), CTAs 136..147 own 6 (96 rows).
//    block 256 = 8 warps (4 m-slots x 2 n); m-slot w handles tiles {w, w+4};
//    B fragments loaded once per kt, reused across the slot's m-tiles.
// ---------------------------------------------------------------------------
__global__ void __launch_bounds__(256, 1) k_gemm() {
    extern __shared__ char smem[];
    const uint32_t sb = smem_u32(smem);
    const int tid = threadIdx.x, lane = tid & 31, wid = tid >> 5;
    const int warp_m = wid & 3, warp_n = wid >> 2;
    const int n_base = warp_n * 64;
    const int q = lane & 3;

    const int bi = blockIdx.x;
    const int big = (bi < 136);
    const int row0 = big ? bi * 112 : 15232 + (bi - 136) * 96;
    const int mtc = big ? 7 : 6;
    const int nt1 = (warp_m < mtc) ? 1 : 0;          // tile warp_m
    const int nt2 = (warp_m + 4 < mtc) ? 1 : 0;      // tile warp_m+4
    const int xunits = mtc * 512;                     // 16B units of X

    // prologue: X tile (swizzled), ce table, E chunk0 via cp.async
#pragma unroll
    for (int j = 0; j < 14; j++) {
        int idx = tid + j * 256;
        if (idx < xunits) {
            int r = idx >> 5, u = idx & 31;
            CP16(sb + SM_X + sw_off(r, u), g_xb + (size_t)(row0 + r) * DIMS + u * 8);
        }
    }
#pragma unroll
    for (int j = 0; j < 8; j++) {
        int idx = tid + j * 256;
        CP16(sb + SM_CE + idx * 16, g_ce + idx * 4);
    }
#pragma unroll
    for (int j = 0; j < 16; j++) {
        int idx = tid + j * 256;
        int r = idx >> 5, u = idx & 31;
        CP16(sb + SM_E0 + sw_off(r, u), g_ebh + (size_t)r * DIMS + u * 8);
    }
    CP_COMMIT();

    const int a_r = (lane & 15), a_u = (lane >> 4);
    const int b_g = lane >> 3;
    const int b_nt = b_g >> 1, b_kh = b_g & 1;
    const int b_r = lane & 7;

    for (int c = 0; c < 64; c++) {
        CP_WAIT0();
        __syncthreads();
        const uint32_t eb = sb + ((c & 1) ? SM_E1 : SM_E0);
        if (c < 63) {
            const uint32_t nb = sb + ((c & 1) ? SM_E0 : SM_E1);
            const __nv_bfloat16* src = g_ebh + (size_t)(c + 1) * 128 * DIMS;
#pragma unroll
            for (int j = 0; j < 16; j++) {
                int idx = tid + j * 256;
                int r = idx >> 5, u = idx & 31;
                CP16(nb + sw_off(r, u), src + (size_t)r * DIMS + u * 8);
            }
            CP_COMMIT();
        }

        float acc[2][8][4];
#pragma unroll
        for (int mi = 0; mi < 2; mi++)
#pragma unroll
            for (int nt = 0; nt < 8; nt++)
#pragma unroll
                for (int z = 0; z < 4; z++) acc[mi][nt][z] = 0.f;

#pragma unroll
        for (int kt = 0; kt < 16; kt++) {
            uint32_t b[8][2];
#pragma unroll
            for (int np = 0; np < 4; np++) {
                uint32_t addr = eb +
                    sw_off(n_base + (np * 2 + b_nt) * 8 + b_r, kt * 2 + b_kh);
                LDSM_X4(b[np * 2][0], b[np * 2][1],
                        b[np * 2 + 1][0], b[np * 2 + 1][1], addr);
            }
            if (nt1) {
                uint32_t a[4];
                uint32_t addr = sb + SM_X +
                    sw_off(warp_m * 16 + a_r, kt * 2 + a_u);
                LDSM_X4(a[0], a[1], a[2], a[3], addr);
#pragma unroll
                for (int nt = 0; nt < 8; nt++) MMA16816(acc[0][nt], a, b[nt]);
            }
            if (nt2) {
                uint32_t a[4];
                uint32_t addr = sb + SM_X +
                    sw_off((warp_m + 4) * 16 + a_r, kt * 2 + a_u);
                LDSM_X4(a[0], a[1], a[2], a[3], addr);
#pragma unroll
                for (int nt = 0; nt < 8; nt++) MMA16816(acc[1][nt], a, b[nt]);
            }
        }

        // epilogue: lane-local min over 8 n-tiles (no shuffles)
        float mn[2][2] = {{3.4e38f, 3.4e38f}, {3.4e38f, 3.4e38f}};
#pragma unroll
        for (int nt = 0; nt < 8; nt++) {
            int col = c * 128 + n_base + nt * 8 + q * 2;
            float2 ce2;
            asm volatile("ld.shared.v2.f32 {%0,%1}, [%2];"
                         : "=f"(ce2.x), "=f"(ce2.y)
                         : "r"(sb + SM_CE + (uint32_t)col * 4));
#pragma unroll
            for (int mi = 0; mi < 2; mi++) {
                float vlo = fminf(fmaf(-2.f, acc[mi][nt][0], ce2.x),
                                  fmaf(-2.f, acc[mi][nt][1], ce2.y));
                float vhi = fminf(fmaf(-2.f, acc[mi][nt][2], ce2.x),
                                  fmaf(-2.f, acc[mi][nt][3], ce2.y));
                mn[mi][0] = fminf(mn[mi][0], vlo);
                mn[mi][1] = fminf(mn[mi][1], vhi);
            }
        }
        const int grp = c * 8 + warp_n * 4 + q;
        if (nt1) {
            int rlo = row0 + warp_m * 16 + (lane >> 2);
            g_cmin[(size_t)rlo * NGROUP + grp] = __float2bfloat16_rn(mn[0][0]);
            g_cmin[(size_t)(rlo + 8) * NGROUP + grp] = __float2bfloat16_rn(mn[0][1]);
        }
        if (nt2) {
            int rlo = row0 + (warp_m + 4) * 16 + (lane >> 2);
            g_cmin[(size_t)rlo * NGROUP + grp] = __float2bfloat16_rn(mn[1][0]);
            g_cmin[(size_t)(rlo + 8) * NGROUP + grp] = __float2bfloat16_rn(mn[1][1]);
        }
    }
}

// ---------------------------------------------------------------------------
// 4) Sweep 2: exact fp32 rescore; warp per row; batches of 4 codes for ILP.
//    group grp -> codes (grp>>3)*128 + ((grp>>2)&1)*64 + (grp&3)*2 + nt*8 + {0,1}
// ---------------------------------------------------------------------------
__global__ void __launch_bounds__(256, 2) k_pick(const float* __restrict__ e) {
    const int tid = threadIdx.x, lane = tid & 31, wid = tid >> 5;
    const int row = blockIdx.x * 8 + wid;

    const uint4* cm4 = (const uint4*)(g_cmin + (size_t)row * NGROUP) + lane * 2;
    float v[16];
    float gmin = 3.402823466e38f;
#pragma unroll
    for (int j = 0; j < 2; j++) {
        uint4 qq = cm4[j];
        const uint32_t w[4] = {qq.x, qq.y, qq.z, qq.w};
#pragma unroll
        for (int h = 0; h < 4; h++) {
            v[j * 8 + h * 2 + 0] = __bfloat162float(__ushort_as_bfloat16((unsigned short)(w[h] & 0xffff)));
            v[j * 8 + h * 2 + 1] = __bfloat162float(__ushort_as_bfloat16((unsigned short)(w[h] >> 16)));
        }
    }
#pragma unroll
    for (int j = 0; j < 16; j++) gmin = fminf(gmin, v[j]);
#pragma unroll
    for (int off = 16; off; off >>= 1)
        gmin = fminf(gmin, __shfl_xor_sync(0xffffffffu, gmin, off));
    const float thr = gmin + MARGIN;

    uint32_t lmask = 0;
#pragma unroll
    for (int j = 0; j < 16; j++) if (v[j] <= thr) lmask |= (1u << j);

    const float4* xr = (const float4*)(g_xr + (size_t)row * DIMS) + lane * 2;
    float4 x0 = xr[0], x1 = xr[1];
    const float xx = g_xx[row];

    float minv = 3.402823466e38f;
    int mini = 0x7fffffff;

    for (int src = 0; src < 32; src++) {
        uint32_t m = __shfl_sync(0xffffffffu, lmask, src);
        while (m) {
            int bit = __ffs(m) - 1;
            m &= m - 1;
            int grp = src * 16 + bit;
            int base = (grp >> 3) * 128 + ((grp >> 2) & 1) * 64 + (grp & 3) * 2;
            // 16 codes in 4 batches of 4: codes base + bq*16 + {0,1,8,9}
#pragma unroll
            for (int bq = 0; bq < 4; bq++) {
                int c0 = base + bq * 16;
                const int codes[4] = {c0, c0 + 1, c0 + 8, c0 + 9};
                float4 E[4][2];
#pragma unroll
                for (int j = 0; j < 4; j++) {
                    const float4* er = (const float4*)(e + (size_t)codes[j] * DIMS) + lane * 2;
                    E[j][0] = er[0];
                    E[j][1] = er[1];
                }
                float t[4];
#pragma unroll
                for (int j = 0; j < 4; j++) {
                    float s = x0.x * E[j][0].x;
                    s = fmaf(x0.y, E[j][0].y, s); s = fmaf(x0.z, E[j][0].z, s);
                    s = fmaf(x0.w, E[j][0].w, s); s = fmaf(x1.x, E[j][1].x, s);
                    s = fmaf(x1.y, E[j][1].y, s); s = fmaf(x1.z, E[j][1].z, s);
                    s = fmaf(x1.w, E[j][1].w, s);
                    t[j] = s;
                }
#pragma unroll
                for (int off = 16; off; off >>= 1) {
                    t[0] += __shfl_xor_sync(0xffffffffu, t[0], off);
                    t[1] += __shfl_xor_sync(0xffffffffu, t[1], off);
                    t[2] += __shfl_xor_sync(0xffffffffu, t[2], off);
                    t[3] += __shfl_xor_sync(0xffffffffu, t[3], off);
                }
#pragma unroll
                for (int j = 0; j < 4; j++) {        // ascending code order
                    float s = (xx + g_ce[codes[j]]) - 2.0f * t[j];
                    if (s < minv || (s == minv && codes[j] < mini)) {
                        minv = s; mini = codes[j];
                    }
                }
            }
        }
    }
    if (lane == 0) {
        g_idx[row] = mini;
        g_minv[row] = minv;
    }
}

// ---------------------------------------------------------------------------
// 5) gather codebook rows -> out (b,c,h,w) + indices
__global__ void k_out(const float* __restrict__ e, float* __restrict__ dout) {
    __shared__ float t[32][33];
    __shared__ int sidx[32];
    const int b = blockIdx.z, c0 = blockIdx.y * 32, hw0 = blockIdx.x * 32;
    const int tx = threadIdx.x, ty = threadIdx.y;
    if (ty == 0) {
        int n = b * 1024 + hw0 + tx;
        int i = g_idx[n];
        sidx[tx] = i;
        if (blockIdx.y == 0) dout[IDX_OFF + n] = (float)i;
    }
    __syncthreads();
#pragma unroll
    for (int j = 0; j < 4; j++)
        t[ty + j * 8][tx] = e[(size_t)sidx[ty + j * 8] * DIMS + c0 + tx];
    __syncthreads();
#pragma unroll
    for (int j = 0; j < 4; j++) {
        int cl = ty + j * 8;
        size_t o = (size_t)b * 262144 + (size_t)(c0 + cl) * 1024 + hw0 + tx;
        dout[o] = t[tx][cl];
    }
}

// 6) loss from per-row winning distances: loss = 1.25 * sum(minv) / OUT_ELEMS
__global__ void k_loss(float* __restrict__ dout) {
    __shared__ double rd[256];
    double s = 0.0;
    for (int i = threadIdx.x; i < N_ROWS; i += 256) s += (double)g_minv[i];
    rd[threadIdx.x] = s;
    __syncthreads();
    for (int st = 128; st; st >>= 1) {
        if (threadIdx.x < st) rd[threadIdx.x] += rd[threadIdx.x + st];
        __syncthreads();
    }
    if (threadIdx.x == 0)
        dout[LOSS_OFF] = (float)(rd[0] * (1.25 / (double)OUT_ELEMS));
}

// ---------------------------------------------------------------------------
extern "C" void kernel_launch(void* const* d_in, const int* in_sizes, int n_in,
                              void* d_out, int out_size) {
    const float* x = (const float*)d_in[0];
    const float* e = (const float*)d_in[1];
    float* out = (float*)d_out;

    cudaFuncSetAttribute(k_gemm, cudaFuncAttributeMaxDynamicSharedMemorySize,
                         SMEM_SZ);

    k_trx<<<dim3(32, 16), dim3(32, 8)>>>(x);
    k_prep_e<<<1024, 256>>>(e);
    k_gemm<<<148, 256, SMEM_SZ>>>();
    k_pick<<<2048, 256>>>(e);
    k_out<<<dim3(32, 8, 16), dim3(32, 8)>>>(e, out);
    k_loss<<<1, 256>>>(out);
}

// round 15
// speedup vs baseline: 1.1207x; 1.1207x over previous
#include <cuda_runtime.h>
#include <cuda_bf16.h>
#include <cstdint>

#define N_ROWS   16384
#define DIMS     256
#define K_CODES  8192
#define OUT_ELEMS 4194304
#define LOSS_OFF  4194304
#define IDX_OFF   4194305
#define NGROUP   1024          // 8192 codes / 8 per lane-local group
#define MARGIN   0.125f

// device scratch (allocation-free rule)
__device__ float g_xr[N_ROWS * DIMS];            // transposed x fp32
__device__ __nv_bfloat16 g_xb[N_ROWS * DIMS];    // transposed x bf16
__device__ __nv_bfloat16 g_ebh[K_CODES * DIMS];  // E bf16
__device__ float g_xx[N_ROWS];
__device__ float g_ce[K_CODES];
__device__ __nv_bfloat16 g_cmin[N_ROWS * NGROUP]; // approx lane-group mins
__device__ int   g_idx[N_ROWS];
__device__ float g_minv[N_ROWS];                  // winning distance per row

// ---------------- PTX helpers ----------------
static __device__ __forceinline__ uint32_t smem_u32(const void* p) {
    uint32_t a;
    asm("{ .reg .u64 t; cvta.to.shared.u64 t, %1; cvt.u32.u64 %0, t; }"
        : "=r"(a) : "l"(p));
    return a;
}
#define CP16(dst, src) asm volatile("cp.async.cg.shared.global [%0], [%1], 16;" :: "r"(dst), "l"(src))
#define CP_COMMIT()    asm volatile("cp.async.commit_group;" ::: "memory")
#define CP_WAIT0()     asm volatile("cp.async.wait_group 0;" ::: "memory")

#define LDSM_X4(r0, r1, r2, r3, a) \
    asm volatile("ldmatrix.sync.aligned.m8n8.x4.shared.b16 {%0,%1,%2,%3}, [%4];" \
        : "=r"(r0), "=r"(r1), "=r"(r2), "=r"(r3) : "r"(a))
#define MMA16816(d, a, b) \
    asm volatile("mma.sync.aligned.m16n8k16.row.col.f32.bf16.bf16.f32 " \
        "{%0,%1,%2,%3}, {%4,%5,%6,%7}, {%8,%9}, {%0,%1,%2,%3};" \
        : "+f"((d)[0]), "+f"((d)[1]), "+f"((d)[2]), "+f"((d)[3]) \
        : "r"((a)[0]), "r"((a)[1]), "r"((a)[2]), "r"((a)[3]), "r"((b)[0]), "r"((b)[1]))

// swizzled 16B-unit offset within a [rows x 512B] tile
static __device__ __forceinline__ uint32_t sw_off(int r, int u) {
    return ((uint32_t)r << 9) + (uint32_t)(((u ^ (r & 7)) & 31) << 4);
}

// SMEM map for k_gemm (bytes)
#define SM_X   0
#define SM_E0  65536
#define SM_E1  131072
#define SM_CE  196608
#define SMEM_SZ 229376

// ---------------------------------------------------------------------------
// 1) fused transpose + xx + bf16: x [b,c,h,w] -> g_xr, g_xb, g_xx
__global__ void k_trx(const float* __restrict__ x) {
    __shared__ float t[256][33];
    __shared__ float sxx[8][33];
    const int b = blockIdx.y, hw0 = blockIdx.x * 32;
    const int tx = threadIdx.x, ty = threadIdx.y;
    const int tid = ty * 32 + tx;
    const int n0 = b * 1024 + hw0;

    float px = 0.f;
#pragma unroll
    for (int j = 0; j < 32; j++) {
        int c = ty + j * 8;
        float v = x[(size_t)b * 262144 + (size_t)c * 1024 + hw0 + tx];
        t[c][tx] = v;
        px = fmaf(v, v, px);
    }
    sxx[ty][tx] = px;
    __syncthreads();

#pragma unroll
    for (int r = 0; r < 32; r++) {
        float v = t[tid][r];
        g_xr[(size_t)(n0 + r) * DIMS + tid] = v;
        g_xb[(size_t)(n0 + r) * DIMS + tid] = __float2bfloat16_rn(v);
    }
    if (tid < 32) {
        float s = 0.f;
#pragma unroll
        for (int j = 0; j < 8; j++) s += sxx[j][tid];
        g_xx[n0 + tid] = s;
    }
}

// 2) E prep: ||e||^2 + bf16 convert (one warp per code row)
__global__ void k_prep_e(const float* __restrict__ e) {
    int w = threadIdx.x >> 5, lane = threadIdx.x & 31;
    int row = blockIdx.x * 8 + w;
    const float4* p = (const float4*)(e + (size_t)row * DIMS);
    float4 v0 = p[lane], v1 = p[lane + 32];
    float s = v0.x * v0.x + v0.y * v0.y + v0.z * v0.z + v0.w * v0.w +
              v1.x * v1.x + v1.y * v1.y + v1.z * v1.z + v1.w * v1.w;
    uint2* q = (uint2*)(g_ebh + (size_t)row * DIMS);
    uint32_t a0 = ((uint32_t)__bfloat16_as_ushort(__float2bfloat16_rn(v0.y)) << 16) |
                  (uint32_t)__bfloat16_as_ushort(__float2bfloat16_rn(v0.x));
    uint32_t a1 = ((uint32_t)__bfloat16_as_ushort(__float2bfloat16_rn(v0.w)) << 16) |
                  (uint32_t)__bfloat16_as_ushort(__float2bfloat16_rn(v0.z));
    uint32_t b0 = ((uint32_t)__bfloat16_as_ushort(__float2bfloat16_rn(v1.y)) << 16) |
                  (uint32_t)__bfloat16_as_ushort(__float2bfloat16_rn(v1.x));
    uint32_t b1 = ((uint32_t)__bfloat16_as_ushort(__float2bfloat16_rn(v1.w)) << 16) |
                  (uint32_t)__bfloat16_as_ushort(__float2bfloat16_rn(v1.z));
    q[lane] = make_uint2(a0, a1);
    q[lane + 32] = make_uint2(b0, b1);
#pragma unroll
    for (int off = 16; off; off >>= 1) s += __shfl_xor_sync(0xffffffffu, s, off);
    if (lane == 0) g_ce[row] = s;
}

// ---------------------------------------------------------------------------
// 3) Sweep 1: bf16 mma.sync GEMM. grid 128 (128 rows each), block 512 =
//    16 warps (4 m x 4 n). Warp tile 32 rows x 32 codes -> 4 warps/SMSP.
//    Lane-local group = 8 codes (2 cols x 4 n-tiles at fixed quad q).
// ---------------------------------------------------------------------------
__global__ void __launch_bounds__(512, 1) k_gemm() {
    extern __shared__ char smem[];
    const uint32_t sb = smem_u32(smem);
    const int tid = threadIdx.x, lane = tid & 31, wid = tid >> 5;
    const int warp_m = wid & 3, warp_n = wid >> 2;       // 4 x 4
    const int m_base = warp_m * 32, n_base = warp_n * 32;
    const int row0 = blockIdx.x * 128;
    const int q = lane & 3;

    // prologue: X tile (swizzled), ce table, E chunk0 via cp.async
#pragma unroll
    for (int j = 0; j < 8; j++) {
        int idx = tid + j * 512;           // 4096 16B units of X
        int r = idx >> 5, u = idx & 31;
        CP16(sb + SM_X + sw_off(r, u), g_xb + (size_t)(row0 + r) * DIMS + u * 8);
    }
#pragma unroll
    for (int j = 0; j < 4; j++) {
        int idx = tid + j * 512;           // 2048 units of ce
        CP16(sb + SM_CE + idx * 16, g_ce + idx * 4);
    }
#pragma unroll
    for (int j = 0; j < 8; j++) {
        int idx = tid + j * 512;           // 4096 units of E chunk 0
        int r = idx >> 5, u = idx & 31;
        CP16(sb + SM_E0 + sw_off(r, u), g_ebh + (size_t)r * DIMS + u * 8);
    }
    CP_COMMIT();

    const int a_r = (lane & 15), a_u = (lane >> 4);
    const int b_g = lane >> 3;                 // 0..3
    const int b_nt = b_g >> 1, b_kh = b_g & 1;
    const int b_r = lane & 7;

    for (int c = 0; c < 64; c++) {
        CP_WAIT0();
        __syncthreads();
        const uint32_t eb = sb + ((c & 1) ? SM_E1 : SM_E0);
        if (c < 63) {
            const uint32_t nb = sb + ((c & 1) ? SM_E0 : SM_E1);
            const __nv_bfloat16* src = g_ebh + (size_t)(c + 1) * 128 * DIMS;
#pragma unroll
            for (int j = 0; j < 8; j++) {
                int idx = tid + j * 512;
                int r = idx >> 5, u = idx & 31;
                CP16(nb + sw_off(r, u), src + (size_t)r * DIMS + u * 8);
            }
            CP_COMMIT();
        }

        float acc[2][4][4];
#pragma unroll
        for (int mt = 0; mt < 2; mt++)
#pragma unroll
            for (int nt = 0; nt < 4; nt++)
#pragma unroll
                for (int z = 0; z < 4; z++) acc[mt][nt][z] = 0.f;

#pragma unroll
        for (int kt = 0; kt < 16; kt++) {
            uint32_t a[2][4], b[4][2];
#pragma unroll
            for (int mt = 0; mt < 2; mt++) {
                uint32_t addr = sb + SM_X +
                    sw_off(m_base + mt * 16 + a_r, kt * 2 + a_u);
                LDSM_X4(a[mt][0], a[mt][1], a[mt][2], a[mt][3], addr);
            }
#pragma unroll
            for (int np = 0; np < 2; np++) {
                uint32_t addr = eb +
                    sw_off(n_base + (np * 2 + b_nt) * 8 + b_r, kt * 2 + b_kh);
                LDSM_X4(b[np * 2][0], b[np * 2][1],
                        b[np * 2 + 1][0], b[np * 2 + 1][1], addr);
            }
#pragma unroll
            for (int mt = 0; mt < 2; mt++)
#pragma unroll
                for (int nt = 0; nt < 4; nt++)
                    MMA16816(acc[mt][nt], a[mt], b[nt]);
        }

        // epilogue: lane-local min over 4 n-tiles (no shuffles)
        float mn[2][2] = {{3.4e38f, 3.4e38f}, {3.4e38f, 3.4e38f}};
#pragma unroll
        for (int nt = 0; nt < 4; nt++) {
            int col = c * 128 + n_base + nt * 8 + q * 2;
            float2 ce2;
            asm volatile("ld.shared.v2.f32 {%0,%1}, [%2];"
                         : "=f"(ce2.x), "=f"(ce2.y)
                         : "r"(sb + SM_CE + (uint32_t)col * 4));
#pragma unroll
            for (int mt = 0; mt < 2; mt++) {
                float vlo = fminf(fmaf(-2.f, acc[mt][nt][0], ce2.x),
                                  fmaf(-2.f, acc[mt][nt][1], ce2.y));
                float vhi = fminf(fmaf(-2.f, acc[mt][nt][2], ce2.x),
                                  fmaf(-2.f, acc[mt][nt][3], ce2.y));
                mn[mt][0] = fminf(mn[mt][0], vlo);
                mn[mt][1] = fminf(mn[mt][1], vhi);
            }
        }
        const int grp = c * 16 + warp_n * 4 + q;
#pragma unroll
        for (int mt = 0; mt < 2; mt++) {
            int rlo = row0 + m_base + mt * 16 + (lane >> 2);
            g_cmin[(size_t)rlo * NGROUP + grp] = __float2bfloat16_rn(mn[mt][0]);
            g_cmin[(size_t)(rlo + 8) * NGROUP + grp] = __float2bfloat16_rn(mn[mt][1]);
        }
    }
}

// ---------------------------------------------------------------------------
// 4) Sweep 2: exact fp32 rescore; warp per row (R11 structure).
//    group grp (8 codes): base = (grp>>4)*128 + ((grp>>2)&3)*32 + (grp&3)*2,
//    codes = base + nt*8 + {0,1}, nt in 0..3
// ---------------------------------------------------------------------------
__global__ void __launch_bounds__(256, 4) k_pick(const float* __restrict__ e) {
    const int tid = threadIdx.x, lane = tid & 31, wid = tid >> 5;
    const int row = blockIdx.x * 8 + wid;

    // lane owns 32 groups: grp = lane*32 + j
    const uint4* cm4 = (const uint4*)(g_cmin + (size_t)row * NGROUP) + lane * 4;
    float v[32];
    float gmin = 3.402823466e38f;
#pragma unroll
    for (int j = 0; j < 4; j++) {
        uint4 qq = cm4[j];
        const uint32_t w[4] = {qq.x, qq.y, qq.z, qq.w};
#pragma unroll
        for (int h = 0; h < 4; h++) {
            v[j * 8 + h * 2 + 0] = __bfloat162float(__ushort_as_bfloat16((unsigned short)(w[h] & 0xffff)));
            v[j * 8 + h * 2 + 1] = __bfloat162float(__ushort_as_bfloat16((unsigned short)(w[h] >> 16)));
        }
    }
#pragma unroll
    for (int j = 0; j < 32; j++) gmin = fminf(gmin, v[j]);
#pragma unroll
    for (int off = 16; off; off >>= 1)
        gmin = fminf(gmin, __shfl_xor_sync(0xffffffffu, gmin, off));
    const float thr = gmin + MARGIN;

    uint32_t lmask = 0;
#pragma unroll
    for (int j = 0; j < 32; j++) if (v[j] <= thr) lmask |= (1u << j);

    const float4* xr = (const float4*)(g_xr + (size_t)row * DIMS) + lane * 2;
    float4 x0 = xr[0], x1 = xr[1];
    const float xx = g_xx[row];

    float minv = 3.402823466e38f;
    int mini = 0x7fffffff;

    for (int src = 0; src < 32; src++) {
        uint32_t m = __shfl_sync(0xffffffffu, lmask, src);
        while (m) {
            int bit = __ffs(m) - 1;
            m &= m - 1;
            int grp = src * 32 + bit;
            int base = (grp >> 4) * 128 + ((grp >> 2) & 3) * 32 + (grp & 3) * 2;
#pragma unroll
            for (int nt = 0; nt < 4; nt++) {
#pragma unroll
                for (int cc = 0; cc < 2; cc++) {
                    int code = base + nt * 8 + cc;
                    const float4* er = (const float4*)(e + (size_t)code * DIMS) + lane * 2;
                    float4 e0 = er[0], e1 = er[1];
                    float t = x0.x * e0.x;
                    t = fmaf(x0.y, e0.y, t); t = fmaf(x0.z, e0.z, t);
                    t = fmaf(x0.w, e0.w, t); t = fmaf(x1.x, e1.x, t);
                    t = fmaf(x1.y, e1.y, t); t = fmaf(x1.z, e1.z, t);
                    t = fmaf(x1.w, e1.w, t);
#pragma unroll
                    for (int off = 16; off; off >>= 1)
                        t += __shfl_xor_sync(0xffffffffu, t, off);
                    float s = (xx + g_ce[code]) - 2.0f * t;
                    if (s < minv || (s == minv && code < mini)) { minv = s; mini = code; }
                }
            }
        }
    }
    if (lane == 0) {
        g_idx[row] = mini;
        g_minv[row] = minv;
    }
}

// ---------------------------------------------------------------------------
// 5) gather codebook rows -> out (b,c,h,w) + indices
__global__ void k_out(const float* __restrict__ e, float* __restrict__ dout) {
    __shared__ float t[32][33];
    __shared__ int sidx[32];
    const int b = blockIdx.z, c0 = blockIdx.y * 32, hw0 = blockIdx.x * 32;
    const int tx = threadIdx.x, ty = threadIdx.y;
    if (ty == 0) {
        int n = b * 1024 + hw0 + tx;
        int i = g_idx[n];
        sidx[tx] = i;
        if (blockIdx.y == 0) dout[IDX_OFF + n] = (float)i;
    }
    __syncthreads();
#pragma unroll
    for (int j = 0; j < 4; j++)
        t[ty + j * 8][tx] = e[(size_t)sidx[ty + j * 8] * DIMS + c0 + tx];
    __syncthreads();
#pragma unroll
    for (int j = 0; j < 4; j++) {
        int cl = ty + j * 8;
        size_t o = (size_t)b * 262144 + (size_t)(c0 + cl) * 1024 + hw0 + tx;
        dout[o] = t[tx][cl];
    }
}

// 6) loss from per-row winning distances: loss = 1.25 * sum(minv) / OUT_ELEMS
__global__ void k_loss(float* __restrict__ dout) {
    __shared__ double rd[256];
    double s = 0.0;
    for (int i = threadIdx.x; i < N_ROWS; i += 256) s += (double)g_minv[i];
    rd[threadIdx.x] = s;
    __syncthreads();
    for (int st = 128; st; st >>= 1) {
        if (threadIdx.x < st) rd[threadIdx.x] += rd[threadIdx.x + st];
        __syncthreads();
    }
    if (threadIdx.x == 0)
        dout[LOSS_OFF] = (float)(rd[0] * (1.25 / (double)OUT_ELEMS));
}

// ---------------------------------------------------------------------------
extern "C" void kernel_launch(void* const* d_in, const int* in_sizes, int n_in,
                              void* d_out, int out_size) {
    const float* x = (const float*)d_in[0];
    const float* e = (const float*)d_in[1];
    float* out = (float*)d_out;

    cudaFuncSetAttribute(k_gemm, cudaFuncAttributeMaxDynamicSharedMemorySize,
                         SMEM_SZ);

    k_trx<<<dim3(32, 16), dim3(32, 8)>>>(x);
    k_prep_e<<<1024, 256>>>(e);
    k_gemm<<<128, 512, SMEM_SZ>>>();
    k_pick<<<2048, 256>>>(e);
    k_out<<<dim3(32, 8, 16), dim3(32, 8)>>>(e, out);
    k_loss<<<1, 256>>>(out);
}

// round 16
// speedup vs baseline: 1.1340x; 1.0118x over previous
#include <cuda_runtime.h>
#include <cuda_bf16.h>
#include <cstdint>

#define N_ROWS   16384
#define DIMS     256
#define K_CODES  8192
#define OUT_ELEMS 4194304
#define LOSS_OFF  4194304
#define IDX_OFF   4194305
#define NGROUP   1024          // 8192 codes / 8 per lane-local group
#define MARGIN   0.125f

// device scratch (allocation-free rule)
__device__ float g_xr[N_ROWS * DIMS];            // transposed x fp32
__device__ __nv_bfloat16 g_xb[N_ROWS * DIMS];    // transposed x bf16
__device__ __nv_bfloat16 g_ebh[K_CODES * DIMS];  // E bf16
__device__ float g_xx[N_ROWS];
__device__ float g_ce[K_CODES];
__device__ __nv_bfloat16 g_cmin[N_ROWS * NGROUP]; // approx lane-group mins
__device__ int   g_idx[N_ROWS];
__device__ float g_minv[N_ROWS];                  // winning distance per row

// ---------------- PTX helpers ----------------
static __device__ __forceinline__ uint32_t smem_u32(const void* p) {
    uint32_t a;
    asm("{ .reg .u64 t; cvta.to.shared.u64 t, %1; cvt.u32.u64 %0, t; }"
        : "=r"(a) : "l"(p));
    return a;
}
#define CP16(dst, src) asm volatile("cp.async.cg.shared.global [%0], [%1], 16;" :: "r"(dst), "l"(src))
#define CP_COMMIT()    asm volatile("cp.async.commit_group;" ::: "memory")
#define CP_WAIT0()     asm volatile("cp.async.wait_group 0;" ::: "memory")

#define LDSM_X4(r0, r1, r2, r3, a) \
    asm volatile("ldmatrix.sync.aligned.m8n8.x4.shared.b16 {%0,%1,%2,%3}, [%4];" \
        : "=r"(r0), "=r"(r1), "=r"(r2), "=r"(r3) : "r"(a))
#define MMA16816(d, a, b) \
    asm volatile("mma.sync.aligned.m16n8k16.row.col.f32.bf16.bf16.f32 " \
        "{%0,%1,%2,%3}, {%4,%5,%6,%7}, {%8,%9}, {%0,%1,%2,%3};" \
        : "+f"((d)[0]), "+f"((d)[1]), "+f"((d)[2]), "+f"((d)[3]) \
        : "r"((a)[0]), "r"((a)[1]), "r"((a)[2]), "r"((a)[3]), "r"((b)[0]), "r"((b)[1]))

// swizzled 16B-unit offset within a [rows x 512B] tile
static __device__ __forceinline__ uint32_t sw_off(int r, int u) {
    return ((uint32_t)r << 9) + (uint32_t)(((u ^ (r & 7)) & 31) << 4);
}

// SMEM map for k_gemm (bytes)
#define SM_X   0
#define SM_E0  65536
#define SM_E1  131072
#define SM_CE  196608
#define SMEM_SZ 229376

// ---------------------------------------------------------------------------
// 1) fused transpose + xx + bf16: x [b,c,h,w] -> g_xr, g_xb, g_xx
__global__ void k_trx(const float* __restrict__ x) {
    __shared__ float t[256][33];
    __shared__ float sxx[8][33];
    const int b = blockIdx.y, hw0 = blockIdx.x * 32;
    const int tx = threadIdx.x, ty = threadIdx.y;
    const int tid = ty * 32 + tx;
    const int n0 = b * 1024 + hw0;

    float px = 0.f;
#pragma unroll
    for (int j = 0; j < 32; j++) {
        int c = ty + j * 8;
        float v = x[(size_t)b * 262144 + (size_t)c * 1024 + hw0 + tx];
        t[c][tx] = v;
        px = fmaf(v, v, px);
    }
    sxx[ty][tx] = px;
    __syncthreads();

#pragma unroll
    for (int r = 0; r < 32; r++) {
        float v = t[tid][r];
        g_xr[(size_t)(n0 + r) * DIMS + tid] = v;
        g_xb[(size_t)(n0 + r) * DIMS + tid] = __float2bfloat16_rn(v);
    }
    if (tid < 32) {
        float s = 0.f;
#pragma unroll
        for (int j = 0; j < 8; j++) s += sxx[j][tid];
        g_xx[n0 + tid] = s;
    }
}

// 2) E prep: ||e||^2 + bf16 convert (one warp per code row)
__global__ void k_prep_e(const float* __restrict__ e) {
    int w = threadIdx.x >> 5, lane = threadIdx.x & 31;
    int row = blockIdx.x * 8 + w;
    const float4* p = (const float4*)(e + (size_t)row * DIMS);
    float4 v0 = p[lane], v1 = p[lane + 32];
    float s = v0.x * v0.x + v0.y * v0.y + v0.z * v0.z + v0.w * v0.w +
              v1.x * v1.x + v1.y * v1.y + v1.z * v1.z + v1.w * v1.w;
    uint2* q = (uint2*)(g_ebh + (size_t)row * DIMS);
    uint32_t a0 = ((uint32_t)__bfloat16_as_ushort(__float2bfloat16_rn(v0.y)) << 16) |
                  (uint32_t)__bfloat16_as_ushort(__float2bfloat16_rn(v0.x));
    uint32_t a1 = ((uint32_t)__bfloat16_as_ushort(__float2bfloat16_rn(v0.w)) << 16) |
                  (uint32_t)__bfloat16_as_ushort(__float2bfloat16_rn(v0.z));
    uint32_t b0 = ((uint32_t)__bfloat16_as_ushort(__float2bfloat16_rn(v1.y)) << 16) |
                  (uint32_t)__bfloat16_as_ushort(__float2bfloat16_rn(v1.x));
    uint32_t b1 = ((uint32_t)__bfloat16_as_ushort(__float2bfloat16_rn(v1.w)) << 16) |
                  (uint32_t)__bfloat16_as_ushort(__float2bfloat16_rn(v1.z));
    q[lane] = make_uint2(a0, a1);
    q[lane + 32] = make_uint2(b0, b1);
#pragma unroll
    for (int off = 16; off; off >>= 1) s += __shfl_xor_sync(0xffffffffu, s, off);
    if (lane == 0) g_ce[row] = s;
}

// ---------------------------------------------------------------------------
// 3) Sweep 1: bf16 mma.sync GEMM. grid 128 (128 rows each), block 512 =
//    16 warps (4 m x 4 n). Warp tile 32 rows x 32 codes -> 4 warps/SMSP.
//    Lane-local group = 8 codes (2 cols x 4 n-tiles at fixed quad q).
// ---------------------------------------------------------------------------
__global__ void __launch_bounds__(512, 1) k_gemm() {
    extern __shared__ char smem[];
    const uint32_t sb = smem_u32(smem);
    const int tid = threadIdx.x, lane = tid & 31, wid = tid >> 5;
    const int warp_m = wid & 3, warp_n = wid >> 2;       // 4 x 4
    const int m_base = warp_m * 32, n_base = warp_n * 32;
    const int row0 = blockIdx.x * 128;
    const int q = lane & 3;

    // prologue: X tile (swizzled), ce table, E chunk0 via cp.async
#pragma unroll
    for (int j = 0; j < 8; j++) {
        int idx = tid + j * 512;           // 4096 16B units of X
        int r = idx >> 5, u = idx & 31;
        CP16(sb + SM_X + sw_off(r, u), g_xb + (size_t)(row0 + r) * DIMS + u * 8);
    }
#pragma unroll
    for (int j = 0; j < 4; j++) {
        int idx = tid + j * 512;           // 2048 units of ce
        CP16(sb + SM_CE + idx * 16, g_ce + idx * 4);
    }
#pragma unroll
    for (int j = 0; j < 8; j++) {
        int idx = tid + j * 512;           // 4096 units of E chunk 0
        int r = idx >> 5, u = idx & 31;
        CP16(sb + SM_E0 + sw_off(r, u), g_ebh + (size_t)r * DIMS + u * 8);
    }
    CP_COMMIT();

    const int a_r = (lane & 15), a_u = (lane >> 4);
    const int b_g = lane >> 3;                 // 0..3
    const int b_nt = b_g >> 1, b_kh = b_g & 1;
    const int b_r = lane & 7;

    for (int c = 0; c < 64; c++) {
        CP_WAIT0();
        __syncthreads();
        const uint32_t eb = sb + ((c & 1) ? SM_E1 : SM_E0);
        if (c < 63) {
            const uint32_t nb = sb + ((c & 1) ? SM_E0 : SM_E1);
            const __nv_bfloat16* src = g_ebh + (size_t)(c + 1) * 128 * DIMS;
#pragma unroll
            for (int j = 0; j < 8; j++) {
                int idx = tid + j * 512;
                int r = idx >> 5, u = idx & 31;
                CP16(nb + sw_off(r, u), src + (size_t)r * DIMS + u * 8);
            }
            CP_COMMIT();
        }

        float acc[2][4][4];
#pragma unroll
        for (int mt = 0; mt < 2; mt++)
#pragma unroll
            for (int nt = 0; nt < 4; nt++)
#pragma unroll
                for (int z = 0; z < 4; z++) acc[mt][nt][z] = 0.f;

#pragma unroll
        for (int kt = 0; kt < 16; kt++) {
            uint32_t a[2][4], b[4][2];
#pragma unroll
            for (int mt = 0; mt < 2; mt++) {
                uint32_t addr = sb + SM_X +
                    sw_off(m_base + mt * 16 + a_r, kt * 2 + a_u);
                LDSM_X4(a[mt][0], a[mt][1], a[mt][2], a[mt][3], addr);
            }
#pragma unroll
            for (int np = 0; np < 2; np++) {
                uint32_t addr = eb +
                    sw_off(n_base + (np * 2 + b_nt) * 8 + b_r, kt * 2 + b_kh);
                LDSM_X4(b[np * 2][0], b[np * 2][1],
                        b[np * 2 + 1][0], b[np * 2 + 1][1], addr);
            }
#pragma unroll
            for (int mt = 0; mt < 2; mt++)
#pragma unroll
                for (int nt = 0; nt < 4; nt++)
                    MMA16816(acc[mt][nt], a[mt], b[nt]);
        }

        // epilogue: lane-local min over 4 n-tiles (no shuffles)
        float mn[2][2] = {{3.4e38f, 3.4e38f}, {3.4e38f, 3.4e38f}};
#pragma unroll
        for (int nt = 0; nt < 4; nt++) {
            int col = c * 128 + n_base + nt * 8 + q * 2;
            float2 ce2;
            asm volatile("ld.shared.v2.f32 {%0,%1}, [%2];"
                         : "=f"(ce2.x), "=f"(ce2.y)
                         : "r"(sb + SM_CE + (uint32_t)col * 4));
#pragma unroll
            for (int mt = 0; mt < 2; mt++) {
                float vlo = fminf(fmaf(-2.f, acc[mt][nt][0], ce2.x),
                                  fmaf(-2.f, acc[mt][nt][1], ce2.y));
                float vhi = fminf(fmaf(-2.f, acc[mt][nt][2], ce2.x),
                                  fmaf(-2.f, acc[mt][nt][3], ce2.y));
                mn[mt][0] = fminf(mn[mt][0], vlo);
                mn[mt][1] = fminf(mn[mt][1], vhi);
            }
        }
        const int grp = c * 16 + warp_n * 4 + q;
#pragma unroll
        for (int mt = 0; mt < 2; mt++) {
            int rlo = row0 + m_base + mt * 16 + (lane >> 2);
            g_cmin[(size_t)rlo * NGROUP + grp] = __float2bfloat16_rn(mn[mt][0]);
            g_cmin[(size_t)(rlo + 8) * NGROUP + grp] = __float2bfloat16_rn(mn[mt][1]);
        }
    }
}

// ---------------------------------------------------------------------------
// 4) Sweep 2: exact fp32 rescore; warp per row. Ballot-driven lane scan:
//    iterate only over lanes that actually hold candidate groups.
//    group grp (8 codes): base = (grp>>4)*128 + ((grp>>2)&3)*32 + (grp&3)*2,
//    codes = base + nt*8 + {0,1}, nt in 0..3
// ---------------------------------------------------------------------------
__global__ void __launch_bounds__(256, 4) k_pick(const float* __restrict__ e) {
    const int tid = threadIdx.x, lane = tid & 31, wid = tid >> 5;
    const int row = blockIdx.x * 8 + wid;

    // lane owns 32 groups: grp = lane*32 + j
    const uint4* cm4 = (const uint4*)(g_cmin + (size_t)row * NGROUP) + lane * 4;
    float v[32];
    float gmin = 3.402823466e38f;
#pragma unroll
    for (int j = 0; j < 4; j++) {
        uint4 qq = cm4[j];
        const uint32_t w[4] = {qq.x, qq.y, qq.z, qq.w};
#pragma unroll
        for (int h = 0; h < 4; h++) {
            v[j * 8 + h * 2 + 0] = __bfloat162float(__ushort_as_bfloat16((unsigned short)(w[h] & 0xffff)));
            v[j * 8 + h * 2 + 1] = __bfloat162float(__ushort_as_bfloat16((unsigned short)(w[h] >> 16)));
        }
    }
#pragma unroll
    for (int j = 0; j < 32; j++) gmin = fminf(gmin, v[j]);
#pragma unroll
    for (int off = 16; off; off >>= 1)
        gmin = fminf(gmin, __shfl_xor_sync(0xffffffffu, gmin, off));
    const float thr = gmin + MARGIN;

    uint32_t lmask = 0;
#pragma unroll
    for (int j = 0; j < 32; j++) if (v[j] <= thr) lmask |= (1u << j);

    const float4* xr = (const float4*)(g_xr + (size_t)row * DIMS) + lane * 2;
    float4 x0 = xr[0], x1 = xr[1];
    const float xx = g_xx[row];

    float minv = 3.402823466e38f;
    int mini = 0x7fffffff;

    // only visit lanes that hold candidates (ascending lane = ascending code)
    uint32_t active = __ballot_sync(0xffffffffu, lmask != 0);
    while (active) {
        int src = __ffs(active) - 1;
        active &= active - 1;
        uint32_t m = __shfl_sync(0xffffffffu, lmask, src);
        while (m) {
            int bit = __ffs(m) - 1;
            m &= m - 1;
            int grp = src * 32 + bit;
            int base = (grp >> 4) * 128 + ((grp >> 2) & 3) * 32 + (grp & 3) * 2;
#pragma unroll
            for (int nt = 0; nt < 4; nt++) {
#pragma unroll
                for (int cc = 0; cc < 2; cc++) {
                    int code = base + nt * 8 + cc;
                    const float4* er = (const float4*)(e + (size_t)code * DIMS) + lane * 2;
                    float4 e0 = er[0], e1 = er[1];
                    float t = x0.x * e0.x;
                    t = fmaf(x0.y, e0.y, t); t = fmaf(x0.z, e0.z, t);
                    t = fmaf(x0.w, e0.w, t); t = fmaf(x1.x, e1.x, t);
                    t = fmaf(x1.y, e1.y, t); t = fmaf(x1.z, e1.z, t);
                    t = fmaf(x1.w, e1.w, t);
#pragma unroll
                    for (int off = 16; off; off >>= 1)
                        t += __shfl_xor_sync(0xffffffffu, t, off);
                    float s = (xx + g_ce[code]) - 2.0f * t;
                    if (s < minv || (s == minv && code < mini)) { minv = s; mini = code; }
                }
            }
        }
    }
    if (lane == 0) {
        g_idx[row] = mini;
        g_minv[row] = minv;
    }
}

// ---------------------------------------------------------------------------
// 5) gather codebook rows -> out (b,c,h,w) + indices
__global__ void k_out(const float* __restrict__ e, float* __restrict__ dout) {
    __shared__ float t[32][33];
    __shared__ int sidx[32];
    const int b = blockIdx.z, c0 = blockIdx.y * 32, hw0 = blockIdx.x * 32;
    const int tx = threadIdx.x, ty = threadIdx.y;
    if (ty == 0) {
        int n = b * 1024 + hw0 + tx;
        int i = g_idx[n];
        sidx[tx] = i;
        if (blockIdx.y == 0) dout[IDX_OFF + n] = (float)i;
    }
    __syncthreads();
#pragma unroll
    for (int j = 0; j < 4; j++)
        t[ty + j * 8][tx] = e[(size_t)sidx[ty + j * 8] * DIMS + c0 + tx];
    __syncthreads();
#pragma unroll
    for (int j = 0; j < 4; j++) {
        int cl = ty + j * 8;
        size_t o = (size_t)b * 262144 + (size_t)(c0 + cl) * 1024 + hw0 + tx;
        dout[o] = t[tx][cl];
    }
}

// 6) loss from per-row winning distances: loss = 1.25 * sum(minv) / OUT_ELEMS
__global__ void k_loss(float* __restrict__ dout) {
    __shared__ double rd[256];
    double s = 0.0;
    for (int i = threadIdx.x; i < N_ROWS; i += 256) s += (double)g_minv[i];
    rd[threadIdx.x] = s;
    __syncthreads();
    for (int st = 128; st; st >>= 1) {
        if (threadIdx.x < st) rd[threadIdx.x] += rd[threadIdx.x + st];
        __syncthreads();
    }
    if (threadIdx.x == 0)
        dout[LOSS_OFF] = (float)(rd[0] * (1.25 / (double)OUT_ELEMS));
}

// ---------------------------------------------------------------------------
extern "C" void kernel_launch(void* const* d_in, const int* in_sizes, int n_in,
                              void* d_out, int out_size) {
    const float* x = (const float*)d_in[0];
    const float* e = (const float*)d_in[1];
    float* out = (float*)d_out;

    cudaFuncSetAttribute(k_gemm, cudaFuncAttributeMaxDynamicSharedMemorySize,
                         SMEM_SZ);

    k_trx<<<dim3(32, 16), dim3(32, 8)>>>(x);
    k_prep_e<<<1024, 256>>>(e);
    k_gemm<<<128, 512, SMEM_SZ>>>();
    k_pick<<<2048, 256>>>(e);
    k_out<<<dim3(32, 8, 16), dim3(32, 8)>>>(e, out);
    k_loss<<<1, 256>>>(out);
}